// round 16
// baseline (speedup 1.0000x reference)
#include <cuda_runtime.h>
#include <cuda_fp16.h>

#define Hh  96
#define Ww  96
#define Dd  48
#define Cc  64
#define HW  (Hh * Ww)        // 9216
#define DHW (Dd * HW)        // 442368
#define P   32               // positions per block (divides Ww)

// Scratch: transposed feats [view][h][w][c] in fp16, imgs [view][h][w][4] fp32
__device__ __half g_feats_t[3 * HW * Cc];   // ~3.54 MB
__device__ float  g_imgs_t [3 * HW * 4];    // ~0.44 MB

// ---- packed f32x2 helpers (sm_103a FFMA2 path; exact fp32 per lane) --------
__device__ __forceinline__ unsigned long long pk2(float a, float b) {
    unsigned long long r;
    asm("mov.b64 %0, {%1, %2};" : "=l"(r) : "f"(a), "f"(b));
    return r;
}
__device__ __forceinline__ void upk2(unsigned long long v, float& a, float& b) {
    asm("mov.b64 {%0, %1}, %2;" : "=f"(a), "=f"(b) : "l"(v));
}
__device__ __forceinline__ unsigned long long mul2(unsigned long long a, unsigned long long b) {
    unsigned long long r;
    asm("mul.rn.f32x2 %0, %1, %2;" : "=l"(r) : "l"(a), "l"(b));
    return r;
}
__device__ __forceinline__ unsigned long long add2(unsigned long long a, unsigned long long b) {
    unsigned long long r;
    asm("add.rn.f32x2 %0, %1, %2;" : "=l"(r) : "l"(a), "l"(b));
    return r;
}
__device__ __forceinline__ unsigned long long fma2(unsigned long long a, unsigned long long b,
                                                   unsigned long long c) {
    unsigned long long r;
    asm("fma.rn.f32x2 %0, %1, %2, %3;" : "=l"(r) : "l"(a), "l"(b), "l"(c));
    return r;
}

// streaming (evict-first) stores: output is write-once, keep feats in L2
__device__ __forceinline__ void stcs1(float* p, float v) {
    asm volatile("st.global.cs.f32 [%0], %1;" :: "l"(p), "f"(v) : "memory");
}
__device__ __forceinline__ void stcs4(float* p, float4 v) {
    asm volatile("st.global.cs.v4.f32 [%0], {%1,%2,%3,%4};"
                 :: "l"(p), "f"(v.x), "f"(v.y), "f"(v.z), "f"(v.w) : "memory");
}

// ---------------------------------------------------------------------------
// Prepass: (C,H,W) -> (H,W,C) transpose per view; feats -> fp16.
// Split into 4 channel-quarters per (v,h) row: 1152 blocks for latency hiding.
// ---------------------------------------------------------------------------
__global__ void __launch_bounds__(256) gridenc_transpose(
    const float* __restrict__ feats,   // (3, 64, 96, 96)
    const float* __restrict__ imgs)    // (3, 3, 96, 96)
{
    int v    = blockIdx.x / (Hh * 4);
    int rem  = blockIdx.x % (Hh * 4);
    int h    = rem >> 2;
    int q    = rem & 3;
    int ch0  = q * 16;                 // channel quarter

    __shared__ float s[Ww * 17];       // s[w*17 + c], c in [0,16)

    // ---- load: float4 along w ----
    const float* fsrc = feats + (size_t)(v * Cc + ch0) * HW + h * Ww;
    for (int i = threadIdx.x; i < 16 * (Ww / 4); i += 256) {
        int c  = i / (Ww / 4);
        int w4 = i - c * (Ww / 4);
        float4 t = *(const float4*)(fsrc + c * HW + w4 * 4);
        int b = (w4 * 4) * 17 + c;
        s[b]      = t.x;
        s[b + 17] = t.y;
        s[b + 34] = t.z;
        s[b + 51] = t.w;
    }
    __syncthreads();

    // ---- store: 8 halves per thread per iter as one uint4 ----
    __half* fdst = g_feats_t + (size_t)(v * HW + h * Ww) * Cc + ch0;
    for (int i = threadIdx.x; i < (Ww * 16) / 8; i += 256) {
        int w  = i >> 1;
        int c0 = (i & 1) << 3;
        const float* sp = &s[w * 17 + c0];
        __half2 h0 = __floats2half2_rn(sp[0], sp[1]);
        __half2 h1 = __floats2half2_rn(sp[2], sp[3]);
        __half2 h2 = __floats2half2_rn(sp[4], sp[5]);
        __half2 h3 = __floats2half2_rn(sp[6], sp[7]);
        uint4 o;
        o.x = *(unsigned*)&h0; o.y = *(unsigned*)&h1;
        o.z = *(unsigned*)&h2; o.w = *(unsigned*)&h3;
        *(uint4*)(fdst + w * Cc + c0) = o;
    }

    // ---- imgs: (3,H,W) -> (H,W,4) fp32; once per (v,h); vectorized store ----
    if (q == 0) {
        const float* isrc = imgs + (size_t)(v * 3) * HW + h * Ww;
        float* idst = g_imgs_t + (size_t)(v * HW + h * Ww) * 4;
        for (int w = threadIdx.x; w < Ww; w += 256) {
            float4 o = make_float4(isrc[w], isrc[HW + w], isrc[2 * HW + w], 0.0f);
            *(float4*)(idst + w * 4) = o;
        }
    }
}

// ---------------------------------------------------------------------------
// Main kernel (R13 structure). Block = 32 consecutive positions, one (d,h)
// row. __launch_bounds__(256, 8) caps regs at 32 -> 8 blocks/SM for better
// latency hiding over the irreducible gather-wavefront floor.
// ---------------------------------------------------------------------------
__global__ void __launch_bounds__(256, 8) gridenc_main(
    const float* __restrict__ imgs,    // (3, 3, 96, 96) - only view0 used
    const float* __restrict__ proj,    // (3, 3, 4)
    const float* __restrict__ depth,   // (48,)
    float* __restrict__ out)           // (73, 48, 96, 96)
{
    __shared__ uint4  s_wh[2][P];      // 4 bilinear weights as duplicated half2
    __shared__ int4   s_o[2][P];       // corner offsets in half-elems (off*64)
    __shared__ float  s_m[2][P];       // in-range flag per view
    __shared__ float  s_var[Cc][P];    // XOR-swizzled: col = p ^ ((c>>3)<<2)

    const int tid  = threadIdx.x;
    const int pos0 = blockIdx.x * P;
    const int hw0  = pos0 % HW;        // block-uniform (P divides row)

    // ---------------- Phase 0: prefetch ref feature vector ------------------
    const int c8 = tid & 7;            // channels c8*8 .. c8*8+7
    const int p2 = tid >> 3;           // 0..31
    const int ce = c8 << 3;
    uint4 rv = *(const uint4*)(g_feats_t + (hw0 + p2) * Cc + ce);

    // ---------------- Phase 1: split across warps 0-2 -----------------------
    if (tid < 64) {
        const int vi = tid >> 5;       // view index (0 -> src view 1)
        const int p  = tid & 31;
        int pos = pos0 + p;
        int w   = (hw0 + p) % Ww;
        int h   = (hw0 + p) / Ww;
        int d   = pos / HW;

        float dep = depth[d];
        float fw = (float)w, fh = (float)h;

        const float* Pm = proj + (vi + 1) * 12;
        float px = Pm[0] * fw + Pm[1] * fh + Pm[2]  + Pm[3]  / dep;
        float py = Pm[4] * fw + Pm[5] * fh + Pm[6]  + Pm[7]  / dep;
        float pz = Pm[8] * fw + Pm[9] * fh + Pm[10] + Pm[11] / dep;
        float gx = (px / pz) / 47.5f - 1.0f;
        float gy = (py / pz) / 47.5f - 1.0f;

        s_m[vi][p] = (gx > -1.0f && gx < 1.0f && gy > -1.0f && gy < 1.0f) ? 1.0f : 0.0f;

        float x = (gx + 1.0f) * 0.5f * 95.0f;
        float y = (gy + 1.0f) * 0.5f * 95.0f;

        float x0f = floorf(x), y0f = floorf(y);
        float fx1 = x - x0f, fy1 = y - y0f;
        float fx0 = 1.0f - fx1, fy0 = 1.0f - fy1;

        // per-corner validity (zeros padding); NaN coords -> all-false
        float vx0 = (x0f >=  0.0f && x0f <= 95.0f) ? 1.0f : 0.0f;
        float vx1 = (x0f >= -1.0f && x0f <= 94.0f) ? 1.0f : 0.0f;
        float vy0 = (y0f >=  0.0f && y0f <= 95.0f) ? 1.0f : 0.0f;
        float vy1 = (y0f >= -1.0f && y0f <= 94.0f) ? 1.0f : 0.0f;

        // per-corner INDEPENDENT clamping (matches reference)
        int ix0 = (int)fminf(fmaxf(x0f,        0.0f), 95.0f);
        int iy0 = (int)fminf(fmaxf(y0f,        0.0f), 95.0f);
        int ix1 = (int)fminf(fmaxf(x0f + 1.0f, 0.0f), 95.0f);
        int iy1 = (int)fminf(fmaxf(y0f + 1.0f, 0.0f), 95.0f);

        float w0 = fx0 * fy0 * vx0 * vy0;
        float w1 = fx1 * fy0 * vx1 * vy0;
        float w2 = fx0 * fy1 * vx0 * vy1;
        float w3 = fx1 * fy1 * vx1 * vy1;

        int vb = (vi + 1) * HW;
        int o0 = vb + iy0 * Ww + ix0;
        int o1 = vb + iy0 * Ww + ix1;
        int o2 = vb + iy1 * Ww + ix0;
        int o3 = vb + iy1 * Ww + ix1;

        // weights as duplicated half2 (for HFMA2 blending in phase 2)
        uint4 wq;
        __half2 h0 = __float2half2_rn(w0);
        __half2 h1 = __float2half2_rn(w1);
        __half2 h2 = __float2half2_rn(w2);
        __half2 h3 = __float2half2_rn(w3);
        wq.x = *(unsigned*)&h0; wq.y = *(unsigned*)&h1;
        wq.z = *(unsigned*)&h2; wq.w = *(unsigned*)&h3;
        s_wh[vi][p] = wq;
        s_o[vi][p] = make_int4(o0 << 6, o1 << 6, o2 << 6, o3 << 6);

        // warped img channels (3 floats) for this view (fp32 path)
        float4 t0 = *(const float4*)(g_imgs_t + (size_t)o0 * 4);
        float4 t1 = *(const float4*)(g_imgs_t + (size_t)o1 * 4);
        float4 t2 = *(const float4*)(g_imgs_t + (size_t)o2 * 4);
        float4 t3 = *(const float4*)(g_imgs_t + (size_t)o3 * 4);
        stcs1(&out[(3 + 3 * vi + 0) * DHW + pos], w0 * t0.x + w1 * t1.x + w2 * t2.x + w3 * t3.x);
        stcs1(&out[(3 + 3 * vi + 1) * DHW + pos], w0 * t0.y + w1 * t1.y + w2 * t2.y + w3 * t3.y);
        stcs1(&out[(3 + 3 * vi + 2) * DHW + pos], w0 * t0.z + w1 * t1.z + w2 * t2.z + w3 * t3.z);
    } else if (tid < 96) {
        const int p  = tid & 31;
        int pos = pos0 + p;
        int hw  = hw0 + p;
        stcs1(&out[0 * DHW + pos], imgs[0 * HW + hw]);
        stcs1(&out[1 * DHW + pos], imgs[1 * HW + hw]);
        stcs1(&out[2 * DHW + pos], imgs[2 * HW + hw]);
    }
    __syncthreads();

    // ---------------- Phase 2: half2 blend, packed f32x2 accumulate ---------
    {
        unsigned long long sac[4], qac[4];
        {
            const __half2* r2 = (const __half2*)&rv;
#pragma unroll
            for (int k = 0; k < 4; ++k) {
                float2 f = __half22float2(r2[k]);
                unsigned long long v = pk2(f.x, f.y);
                sac[k] = v;
                qac[k] = mul2(v, v);
            }
        }

#pragma unroll
        for (int vi = 0; vi < 2; ++vi) {
            uint4 wq = s_wh[vi][p2];
            __half2 w0 = *(__half2*)&wq.x, w1 = *(__half2*)&wq.y;
            __half2 w2 = *(__half2*)&wq.z, w3 = *(__half2*)&wq.w;
            int4 ov = s_o[vi][p2];
            uint4 va = *(const uint4*)(g_feats_t + ov.x + ce);
            uint4 vb = *(const uint4*)(g_feats_t + ov.y + ce);
            uint4 vc = *(const uint4*)(g_feats_t + ov.z + ce);
            uint4 ve = *(const uint4*)(g_feats_t + ov.w + ce);
            const __half2* a2 = (const __half2*)&va;
            const __half2* b2 = (const __half2*)&vb;
            const __half2* c2 = (const __half2*)&vc;
            const __half2* e2 = (const __half2*)&ve;
#pragma unroll
            for (int k = 0; k < 4; ++k) {
                __half2 m2 = __hmul2(w0, a2[k]);
                m2 = __hfma2(w1, b2[k], m2);
                m2 = __hfma2(w2, c2[k], m2);
                m2 = __hfma2(w3, e2[k], m2);
                float2 mf = __half22float2(m2);
                unsigned long long mm = pk2(mf.x, mf.y);
                sac[k] = add2(sac[k], mm);
                qac[k] = fma2(mm, mm, qac[k]);
            }
        }

        float nm  = 1.0f + s_m[0][p2] + s_m[1][p2];
        float inv = 1.0f / nm;
        unsigned long long iv = pk2(inv, inv);
        const int col = p2 ^ (c8 << 2);   // XOR swizzle -> conflict-free STS
#pragma unroll
        for (int k = 0; k < 4; ++k) {
            unsigned long long m  = mul2(sac[k], iv);
            unsigned long long qi = mul2(qac[k], iv);
            unsigned long long nmg = m ^ 0x8000000080000000ULL;  // -m per lane
            unsigned long long vr = fma2(m, nmg, qi);            // qi - m*m
            float v0, v1;
            upk2(vr, v0, v1);
            s_var[ce + 2 * k + 0][col] = v0;
            s_var[ce + 2 * k + 1][col] = v1;
        }
    }
    __syncthreads();

    // ---------------- Phase 3: vectorized variance stores -------------------
    // warp cw handles channels c = it*8 + cw. Lane = ch4*8 + g covers 4 its
    // at once; float4 spans 4 consecutive positions (XOR swizzle is linear:
    // cols 4*(g^it)+r  <->  positions 4g+r).
    {
        const int g   = tid & 7;
        const int ch4 = (tid >> 3) & 3;
        const int cw  = tid >> 5;
#pragma unroll
        for (int ib = 0; ib < 8; ib += 4) {
            int it = ib + ch4;
            int c  = it * 8 + cw;
            float4 v = *(const float4*)&s_var[c][4 * (g ^ it)];
            stcs4(&out[(9 + c) * DHW + pos0 + 4 * g], v);
        }
    }
}

// ---------------------------------------------------------------------------
// kernel_launch: graph-capturable, allocation-free.
// Inputs identified by element count (all distinct):
//   imgs=82944; feats=1769472; proj_mats=36; depth_values=48.
// ---------------------------------------------------------------------------
extern "C" void kernel_launch(void* const* d_in, const int* in_sizes, int n_in,
                              void* d_out, int out_size)
{
    const float* imgs  = nullptr;
    const float* feats = nullptr;
    const float* proj  = nullptr;
    const float* depth = nullptr;
    for (int i = 0; i < n_in; ++i) {
        switch (in_sizes[i]) {
            case 3 * 3 * HW:  imgs  = (const float*)d_in[i]; break;
            case 3 * Cc * HW: feats = (const float*)d_in[i]; break;
            case 36:          proj  = (const float*)d_in[i]; break;
            case Dd:          depth = (const float*)d_in[i]; break;
        }
    }
    float* out = (float*)d_out;

    gridenc_transpose<<<3 * Hh * 4, 256>>>(feats, imgs);
    gridenc_main<<<DHW / P, 256>>>(imgs, proj, depth, out);
}

// round 17
// speedup vs baseline: 1.0632x; 1.0632x over previous
#include <cuda_runtime.h>
#include <cuda_fp16.h>

#define Hh  96
#define Ww  96
#define Dd  48
#define Cc  64
#define HW  (Hh * Ww)        // 9216
#define DHW (Dd * HW)        // 442368
#define P   32               // positions per block (divides Ww)
#define NBH (HW / P)         // 288 blocks per depth-pair row

// Scratch: transposed feats [view][h][w][c] in fp16, imgs [view][h][w][4] fp32
__device__ __half g_feats_t[3 * HW * Cc];   // ~3.54 MB
__device__ float  g_imgs_t [3 * HW * 4];    // ~0.44 MB

// ---- packed f32x2 helpers (sm_103a FFMA2 path; exact fp32 per lane) --------
__device__ __forceinline__ unsigned long long pk2(float a, float b) {
    unsigned long long r;
    asm("mov.b64 %0, {%1, %2};" : "=l"(r) : "f"(a), "f"(b));
    return r;
}
__device__ __forceinline__ void upk2(unsigned long long v, float& a, float& b) {
    asm("mov.b64 {%0, %1}, %2;" : "=f"(a), "=f"(b) : "l"(v));
}
__device__ __forceinline__ unsigned long long mul2(unsigned long long a, unsigned long long b) {
    unsigned long long r;
    asm("mul.rn.f32x2 %0, %1, %2;" : "=l"(r) : "l"(a), "l"(b));
    return r;
}
__device__ __forceinline__ unsigned long long add2(unsigned long long a, unsigned long long b) {
    unsigned long long r;
    asm("add.rn.f32x2 %0, %1, %2;" : "=l"(r) : "l"(a), "l"(b));
    return r;
}
__device__ __forceinline__ unsigned long long fma2(unsigned long long a, unsigned long long b,
                                                   unsigned long long c) {
    unsigned long long r;
    asm("fma.rn.f32x2 %0, %1, %2, %3;" : "=l"(r) : "l"(a), "l"(b), "l"(c));
    return r;
}

// streaming (evict-first) stores: output is write-once, keep feats in L2
__device__ __forceinline__ void stcs1(float* p, float v) {
    asm volatile("st.global.cs.f32 [%0], %1;" :: "l"(p), "f"(v) : "memory");
}
__device__ __forceinline__ void stcs4(float* p, float4 v) {
    asm volatile("st.global.cs.v4.f32 [%0], {%1,%2,%3,%4};"
                 :: "l"(p), "f"(v.x), "f"(v.y), "f"(v.z), "f"(v.w) : "memory");
}

// ---------------------------------------------------------------------------
// Prepass: (C,H,W) -> (H,W,C) transpose per view; feats -> fp16.
// Split into 4 channel-quarters per (v,h) row: 1152 blocks for latency hiding.
// ---------------------------------------------------------------------------
__global__ void __launch_bounds__(256) gridenc_transpose(
    const float* __restrict__ feats,   // (3, 64, 96, 96)
    const float* __restrict__ imgs)    // (3, 3, 96, 96)
{
    int v    = blockIdx.x / (Hh * 4);
    int rem  = blockIdx.x % (Hh * 4);
    int h    = rem >> 2;
    int q    = rem & 3;
    int ch0  = q * 16;                 // channel quarter

    __shared__ float s[Ww * 17];       // s[w*17 + c], c in [0,16)

    const float* fsrc = feats + (size_t)(v * Cc + ch0) * HW + h * Ww;
    for (int i = threadIdx.x; i < 16 * (Ww / 4); i += 256) {
        int c  = i / (Ww / 4);
        int w4 = i - c * (Ww / 4);
        float4 t = *(const float4*)(fsrc + c * HW + w4 * 4);
        int b = (w4 * 4) * 17 + c;
        s[b]      = t.x;
        s[b + 17] = t.y;
        s[b + 34] = t.z;
        s[b + 51] = t.w;
    }
    __syncthreads();

    __half* fdst = g_feats_t + (size_t)(v * HW + h * Ww) * Cc + ch0;
    for (int i = threadIdx.x; i < (Ww * 16) / 8; i += 256) {
        int w  = i >> 1;
        int c0 = (i & 1) << 3;
        const float* sp = &s[w * 17 + c0];
        __half2 h0 = __floats2half2_rn(sp[0], sp[1]);
        __half2 h1 = __floats2half2_rn(sp[2], sp[3]);
        __half2 h2 = __floats2half2_rn(sp[4], sp[5]);
        __half2 h3 = __floats2half2_rn(sp[6], sp[7]);
        uint4 o;
        o.x = *(unsigned*)&h0; o.y = *(unsigned*)&h1;
        o.z = *(unsigned*)&h2; o.w = *(unsigned*)&h3;
        *(uint4*)(fdst + w * Cc + c0) = o;
    }

    if (q == 0) {
        const float* isrc = imgs + (size_t)(v * 3) * HW + h * Ww;
        float* idst = g_imgs_t + (size_t)(v * HW + h * Ww) * 4;
        for (int w = threadIdx.x; w < Ww; w += 256) {
            float4 o = make_float4(isrc[w], isrc[HW + w], isrc[2 * HW + w], 0.0f);
            *(float4*)(idst + w * 4) = o;
        }
    }
}

// ---------------------------------------------------------------------------
// Main kernel, depth-paired: block = 32 consecutive positions at 2 consecutive
// depths (same hw window). Ref-feature gather and all per-position params are
// amortized across both depths; barriers per position halved.
// Phase 0 (all): prefetch ref vector (depth-invariant).
// Phase 1: warps 0-3 = geometry+img-warp (dd, vi); warps 4-5 = broadcast.
// Phase 2: loop dd: dense fp16 gathers, half2 blend, f32x2 accumulate.
// Phase 3: loop dd: vectorized coalesced variance stores.
// ---------------------------------------------------------------------------
__global__ void __launch_bounds__(256) gridenc_main(
    const float* __restrict__ imgs,    // (3, 3, 96, 96) - only view0 used
    const float* __restrict__ proj,    // (3, 3, 4)
    const float* __restrict__ depth,   // (48,)
    float* __restrict__ out)           // (73, 48, 96, 96)
{
    __shared__ uint4  s_wh[2][2][P];   // [dd][vi][p] weights as dup half2
    __shared__ int4   s_o [2][2][P];   // [dd][vi][p] corner offsets (elems*64)
    __shared__ float  s_m [2][2][P];   // [dd][vi][p] in-range flag
    __shared__ float  s_var[2][Cc][P]; // [dd]; XOR-swizzled col = p ^ ((c>>3)<<2)

    const int tid = threadIdx.x;
    const int blk = blockIdx.x;
    const int d0  = (blk / NBH) * 2;
    const int hw0 = (blk % NBH) * P;

    // ---------------- Phase 0: prefetch ref feature vector ------------------
    const int c8 = tid & 7;            // channels c8*8 .. c8*8+7
    const int p2 = tid >> 3;           // 0..31
    const int ce = c8 << 3;
    uint4 rv = *(const uint4*)(g_feats_t + (hw0 + p2) * Cc + ce);

    // ---------------- Phase 1: warps 0-3 geometry, warps 4-5 broadcast ------
    if (tid < 128) {
        const int dd = tid >> 6;       // depth offset 0/1
        const int vi = (tid >> 5) & 1; // view index (0 -> src view 1)
        const int p  = tid & 31;
        int hw  = hw0 + p;
        int d   = d0 + dd;
        int pos = d * HW + hw;
        int w   = hw % Ww;
        int h   = hw / Ww;

        float dep = depth[d];
        float fw = (float)w, fh = (float)h;

        const float* Pm = proj + (vi + 1) * 12;
        float px = Pm[0] * fw + Pm[1] * fh + Pm[2]  + Pm[3]  / dep;
        float py = Pm[4] * fw + Pm[5] * fh + Pm[6]  + Pm[7]  / dep;
        float pz = Pm[8] * fw + Pm[9] * fh + Pm[10] + Pm[11] / dep;
        float gx = (px / pz) / 47.5f - 1.0f;
        float gy = (py / pz) / 47.5f - 1.0f;

        s_m[dd][vi][p] = (gx > -1.0f && gx < 1.0f && gy > -1.0f && gy < 1.0f) ? 1.0f : 0.0f;

        float x = (gx + 1.0f) * 0.5f * 95.0f;
        float y = (gy + 1.0f) * 0.5f * 95.0f;

        float x0f = floorf(x), y0f = floorf(y);
        float fx1 = x - x0f, fy1 = y - y0f;
        float fx0 = 1.0f - fx1, fy0 = 1.0f - fy1;

        // per-corner validity (zeros padding); NaN coords -> all-false
        float vx0 = (x0f >=  0.0f && x0f <= 95.0f) ? 1.0f : 0.0f;
        float vx1 = (x0f >= -1.0f && x0f <= 94.0f) ? 1.0f : 0.0f;
        float vy0 = (y0f >=  0.0f && y0f <= 95.0f) ? 1.0f : 0.0f;
        float vy1 = (y0f >= -1.0f && y0f <= 94.0f) ? 1.0f : 0.0f;

        // per-corner INDEPENDENT clamping (matches reference)
        int ix0 = (int)fminf(fmaxf(x0f,        0.0f), 95.0f);
        int iy0 = (int)fminf(fmaxf(y0f,        0.0f), 95.0f);
        int ix1 = (int)fminf(fmaxf(x0f + 1.0f, 0.0f), 95.0f);
        int iy1 = (int)fminf(fmaxf(y0f + 1.0f, 0.0f), 95.0f);

        float w0 = fx0 * fy0 * vx0 * vy0;
        float w1 = fx1 * fy0 * vx1 * vy0;
        float w2 = fx0 * fy1 * vx0 * vy1;
        float w3 = fx1 * fy1 * vx1 * vy1;

        int vb = (vi + 1) * HW;
        int o0 = vb + iy0 * Ww + ix0;
        int o1 = vb + iy0 * Ww + ix1;
        int o2 = vb + iy1 * Ww + ix0;
        int o3 = vb + iy1 * Ww + ix1;

        uint4 wq;
        __half2 h0 = __float2half2_rn(w0);
        __half2 h1 = __float2half2_rn(w1);
        __half2 h2 = __float2half2_rn(w2);
        __half2 h3 = __float2half2_rn(w3);
        wq.x = *(unsigned*)&h0; wq.y = *(unsigned*)&h1;
        wq.z = *(unsigned*)&h2; wq.w = *(unsigned*)&h3;
        s_wh[dd][vi][p] = wq;
        s_o[dd][vi][p] = make_int4(o0 << 6, o1 << 6, o2 << 6, o3 << 6);

        // warped img channels (3 floats) for this (dd, vi)
        float4 t0 = *(const float4*)(g_imgs_t + (size_t)o0 * 4);
        float4 t1 = *(const float4*)(g_imgs_t + (size_t)o1 * 4);
        float4 t2 = *(const float4*)(g_imgs_t + (size_t)o2 * 4);
        float4 t3 = *(const float4*)(g_imgs_t + (size_t)o3 * 4);
        stcs1(&out[(3 + 3 * vi + 0) * DHW + pos], w0 * t0.x + w1 * t1.x + w2 * t2.x + w3 * t3.x);
        stcs1(&out[(3 + 3 * vi + 1) * DHW + pos], w0 * t0.y + w1 * t1.y + w2 * t2.y + w3 * t3.y);
        stcs1(&out[(3 + 3 * vi + 2) * DHW + pos], w0 * t0.z + w1 * t1.z + w2 * t2.z + w3 * t3.z);
    } else if (tid < 192) {
        const int dd = (tid >> 5) & 1;
        const int p  = tid & 31;
        int hw  = hw0 + p;
        int pos = (d0 + dd) * HW + hw;
        stcs1(&out[0 * DHW + pos], imgs[0 * HW + hw]);
        stcs1(&out[1 * DHW + pos], imgs[1 * HW + hw]);
        stcs1(&out[2 * DHW + pos], imgs[2 * HW + hw]);
    }
    __syncthreads();

    // ---------------- Phase 2: per-depth gathers, shared ref ----------------
    {
        // ref as packed f32x2 pairs, reused for both depths
        unsigned long long rpk[4];
        {
            const __half2* r2 = (const __half2*)&rv;
#pragma unroll
            for (int k = 0; k < 4; ++k) {
                float2 f = __half22float2(r2[k]);
                rpk[k] = pk2(f.x, f.y);
            }
        }
        const int col = p2 ^ (c8 << 2);   // XOR swizzle -> conflict-free STS

#pragma unroll
        for (int dd = 0; dd < 2; ++dd) {
            unsigned long long sac[4], qac[4];
#pragma unroll
            for (int k = 0; k < 4; ++k) {
                sac[k] = rpk[k];
                qac[k] = mul2(rpk[k], rpk[k]);
            }

#pragma unroll
            for (int vi = 0; vi < 2; ++vi) {
                uint4 wq = s_wh[dd][vi][p2];
                __half2 w0 = *(__half2*)&wq.x, w1 = *(__half2*)&wq.y;
                __half2 w2 = *(__half2*)&wq.z, w3 = *(__half2*)&wq.w;
                int4 ov = s_o[dd][vi][p2];
                uint4 va = *(const uint4*)(g_feats_t + ov.x + ce);
                uint4 vb = *(const uint4*)(g_feats_t + ov.y + ce);
                uint4 vc = *(const uint4*)(g_feats_t + ov.z + ce);
                uint4 ve = *(const uint4*)(g_feats_t + ov.w + ce);
                const __half2* a2 = (const __half2*)&va;
                const __half2* b2 = (const __half2*)&vb;
                const __half2* c2 = (const __half2*)&vc;
                const __half2* e2 = (const __half2*)&ve;
#pragma unroll
                for (int k = 0; k < 4; ++k) {
                    __half2 m2 = __hmul2(w0, a2[k]);
                    m2 = __hfma2(w1, b2[k], m2);
                    m2 = __hfma2(w2, c2[k], m2);
                    m2 = __hfma2(w3, e2[k], m2);
                    float2 mf = __half22float2(m2);
                    unsigned long long mm = pk2(mf.x, mf.y);
                    sac[k] = add2(sac[k], mm);
                    qac[k] = fma2(mm, mm, qac[k]);
                }
            }

            float nm  = 1.0f + s_m[dd][0][p2] + s_m[dd][1][p2];
            float inv = 1.0f / nm;
            unsigned long long iv = pk2(inv, inv);
#pragma unroll
            for (int k = 0; k < 4; ++k) {
                unsigned long long m  = mul2(sac[k], iv);
                unsigned long long qi = mul2(qac[k], iv);
                unsigned long long nmg = m ^ 0x8000000080000000ULL;  // -m
                unsigned long long vr = fma2(m, nmg, qi);            // qi - m*m
                float v0, v1;
                upk2(vr, v0, v1);
                s_var[dd][ce + 2 * k + 0][col] = v0;
                s_var[dd][ce + 2 * k + 1][col] = v1;
            }
        }
    }
    __syncthreads();

    // ---------------- Phase 3: vectorized variance stores (both depths) -----
    {
        const int g   = tid & 7;
        const int ch4 = (tid >> 3) & 3;
        const int cw  = tid >> 5;
#pragma unroll
        for (int dd = 0; dd < 2; ++dd) {
            int base = (d0 + dd) * HW + hw0 + 4 * g;
#pragma unroll
            for (int ib = 0; ib < 8; ib += 4) {
                int it = ib + ch4;
                int c  = it * 8 + cw;
                float4 v = *(const float4*)&s_var[dd][c][4 * (g ^ it)];
                stcs4(&out[(9 + c) * DHW + base], v);
            }
        }
    }
}

// ---------------------------------------------------------------------------
// kernel_launch: graph-capturable, allocation-free.
// Inputs identified by element count (all distinct):
//   imgs=82944; feats=1769472; proj_mats=36; depth_values=48.
// ---------------------------------------------------------------------------
extern "C" void kernel_launch(void* const* d_in, const int* in_sizes, int n_in,
                              void* d_out, int out_size)
{
    const float* imgs  = nullptr;
    const float* feats = nullptr;
    const float* proj  = nullptr;
    const float* depth = nullptr;
    for (int i = 0; i < n_in; ++i) {
        switch (in_sizes[i]) {
            case 3 * 3 * HW:  imgs  = (const float*)d_in[i]; break;
            case 3 * Cc * HW: feats = (const float*)d_in[i]; break;
            case 36:          proj  = (const float*)d_in[i]; break;
            case Dd:          depth = (const float*)d_in[i]; break;
        }
    }
    float* out = (float*)d_out;

    gridenc_transpose<<<3 * Hh * 4, 256>>>(feats, imgs);
    gridenc_main<<<(Dd / 2) * NBH, 256>>>(imgs, proj, depth, out);
}